// round 1
// baseline (speedup 1.0000x reference)
#include <cuda_runtime.h>

#define B_  16
#define C_  512
#define H_  64
#define W_  64
#define WD_ 512
#define EPS_ 1e-6f

// Scratch (allocation-free rule: __device__ globals)
__device__ float g_style[B_ * C_];
__device__ float g_S[C_ * C_];
__device__ float g_rdenom[B_ * C_];

// style[b,o] = dot(w[b,:], linear_w[o,:]) + linear_b[o]
__global__ void style_kernel(const float* __restrict__ w,
                             const float* __restrict__ lw,
                             const float* __restrict__ lb) {
    __shared__ float ws[WD_];
    int b = blockIdx.x, o = threadIdx.x;
    ws[o] = w[b * WD_ + o];
    __syncthreads();
    const float* lwr = lw + o * WD_;
    float acc = lb[o];
#pragma unroll 8
    for (int d = 0; d < WD_; d++) acc = fmaf(ws[d], lwr[d], acc);
    g_style[b * C_ + o] = acc;
}

// S[o,i] = sum_k conv_weight[o,i,k]^2
__global__ void s_kernel(const float* __restrict__ cw) {
    int o = blockIdx.x, i = threadIdx.x;
    const float* p = cw + (o * C_ + i) * 9;
    float s = 0.f;
#pragma unroll
    for (int k = 0; k < 9; k++) { float v = p[k]; s = fmaf(v, v, s); }
    g_S[o * C_ + i] = s;
}

// rdenom[b,o] = rsqrt(sum_i S[o,i]*style[b,i]^2 + eps)
__global__ void rdenom_kernel() {
    __shared__ float st2[C_];
    int b = blockIdx.x, o = threadIdx.x;
    float s = g_style[b * C_ + o];
    st2[o] = s * s;
    __syncthreads();
    const float* Sr = g_S + o * C_;
    float acc = EPS_;
#pragma unroll 8
    for (int i = 0; i < C_; i++) acc = fmaf(Sr[i], st2[i], acc);
    g_rdenom[b * C_ + o] = rsqrtf(acc);
}

// ---------------- main conv ----------------
// Block: one batch b, OT=32 output channels, spatial tile TH=8 x TW=32.
// Thread (256/block): TM=4 output channels x TN=8 consecutive pixels.
// Input-channel chunks of ICH=16 staged in smem; style folded into the
// weight smem tile; demodulation folded into the epilogue.
#define OT  32
#define TH  8
#define TW  32
#define ICH 16
#define TM  4
#define TN  8

__global__ __launch_bounds__(256)
void conv_kernel(const float* __restrict__ x,
                 const float* __restrict__ cw,
                 float* __restrict__ out) {
    __shared__ float in_s[ICH][TH + 2][TW + 2];
    __shared__ float w_s[ICH][9][OT];

    const int b    = blockIdx.z;
    const int oc0  = blockIdx.y * OT;
    const int trow = blockIdx.x >> 1;   // 8 row-tiles
    const int tcol = blockIdx.x & 1;    // 2 col-tiles
    const int t    = threadIdx.x;
    const int og   = t >> 5;            // 0..7  (warp-uniform -> smem broadcast)
    const int pg   = t & 31;
    const int prow = pg >> 2;           // 0..7
    const int pcb  = (pg & 3) * TN;     // 0,8,16,24

    float acc[TM][TN];
#pragma unroll
    for (int m = 0; m < TM; m++)
#pragma unroll
        for (int j = 0; j < TN; j++) acc[m][j] = 0.f;

    const float* style_b = g_style + b * C_;

    for (int ci0 = 0; ci0 < C_; ci0 += ICH) {
        __syncthreads();
        // Weights, pre-scaled by style[b, i]  (gmem reads coalesced over (i,k))
        for (int idx = t; idx < ICH * 9 * OT; idx += 256) {
            int ol  = idx / (ICH * 9);
            int rem = idx % (ICH * 9);
            int ic  = rem / 9;
            int k   = rem % 9;
            float sv = __ldg(style_b + ci0 + ic);
            w_s[ic][k][ol] = cw[((oc0 + ol) * C_ + ci0 + ic) * 9 + k] * sv;
        }
        // Input tile with halo, zero-padded borders (coalesced 34-wide runs)
        for (int idx = t; idx < ICH * (TH + 2) * (TW + 2); idx += 256) {
            int ic = idx / ((TH + 2) * (TW + 2));
            int r  = (idx / (TW + 2)) % (TH + 2);
            int c  = idx % (TW + 2);
            int gy = trow * TH - 1 + r;
            int gx = tcol * TW - 1 + c;
            float v = 0.f;
            if ((unsigned)gy < H_ && (unsigned)gx < W_)
                v = x[((b * C_ + ci0 + ic) * H_ + gy) * W_ + gx];
            in_s[ic][r][c] = v;
        }
        __syncthreads();

        for (int ic = 0; ic < ICH; ic++) {
#pragma unroll
            for (int kh = 0; kh < 3; kh++) {
                float inr[TN + 2];
#pragma unroll
                for (int c = 0; c < TN + 2; c++)
                    inr[c] = in_s[ic][prow + kh][pcb + c];
#pragma unroll
                for (int kw = 0; kw < 3; kw++) {
                    float wv[TM];
#pragma unroll
                    for (int m = 0; m < TM; m++)
                        wv[m] = w_s[ic][kh * 3 + kw][og * TM + m];
#pragma unroll
                    for (int m = 0; m < TM; m++)
#pragma unroll
                        for (int j = 0; j < TN; j++)
                            acc[m][j] = fmaf(wv[m], inr[kw + j], acc[m][j]);
                }
            }
        }
    }

    const int oy  = trow * TH + prow;
    const int ox0 = tcol * TW + pcb;
#pragma unroll
    for (int m = 0; m < TM; m++) {
        int o = oc0 + og * TM + m;
        float rd = g_rdenom[b * C_ + o];
        float* op = out + ((b * C_ + o) * H_ + oy) * W_ + ox0;
#pragma unroll
        for (int j = 0; j < TN; j++) op[j] = acc[m][j] * rd;
    }
}

extern "C" void kernel_launch(void* const* d_in, const int* in_sizes, int n_in,
                              void* d_out, int out_size) {
    const float* x  = (const float*)d_in[0];   // (16,512,64,64)
    const float* w  = (const float*)d_in[1];   // (16,512)
    const float* cw = (const float*)d_in[2];   // (512,512,3,3)
    const float* lw = (const float*)d_in[3];   // (512,512)
    const float* lb = (const float*)d_in[4];   // (512,)
    float* out = (float*)d_out;                // (16,512,64,64) fp32

    style_kernel<<<B_, C_>>>(w, lw, lb);
    s_kernel<<<C_, C_>>>(cw);
    rdenom_kernel<<<B_, C_>>>();

    dim3 grid((H_ / TH) * (W_ / TW), C_ / OT, B_);   // (16, 16, 16)
    conv_kernel<<<grid, 256>>>(x, cw, out);
}

// round 3
// speedup vs baseline: 3.6973x; 3.6973x over previous
#include <cuda_runtime.h>
#include <cstdint>

#define B_   16
#define C_   512
#define HW_  4096
#define W64  64
#define WD_  512
#define EPS_ 1e-6f

// ---------------- scratch (__device__ globals; no runtime alloc) ----------------
__device__ float g_style[B_ * C_];
__device__ float g_S[C_ * C_];
__device__ float g_rdenom[B_ * C_];
__device__ float g_xt[(size_t)B_ * HW_ * C_];   // (b, p, i): style-scaled, tf32-rounded
__device__ float g_cwt[(size_t)9 * C_ * C_];    // (tap, o, i): tf32-rounded

// ---------------- helpers ----------------
__device__ __forceinline__ uint32_t smem_u32(const void* p) {
    uint32_t a;
    asm("{ .reg .u64 t; cvta.to.shared.u64 t, %1; cvt.u32.u64 %0, t; }" : "=r"(a) : "l"(p));
    return a;
}
__device__ __forceinline__ float tf32r(float x) {   // round-to-nearest tf32
    uint32_t u;
    asm("cvt.rna.tf32.f32 %0, %1;" : "=r"(u) : "f"(x));
    return __uint_as_float(u);
}
__device__ __forceinline__ void cp16(uint32_t dst, const void* src, uint32_t src_bytes) {
    asm volatile("cp.async.cg.shared.global [%0], [%1], 16, %2;"
                 :: "r"(dst), "l"(src), "r"(src_bytes));
}
template <int N>
__device__ __forceinline__ void cp_wait() {
    asm volatile("cp.async.wait_group %0;" :: "n"(N) : "memory");
}
__device__ __forceinline__ void cp_commit() {
    asm volatile("cp.async.commit_group;" ::: "memory");
}
__device__ __forceinline__ void mma_tf32(float* d, const uint32_t* a, const uint32_t* bf) {
    asm volatile(
        "mma.sync.aligned.m16n8k8.row.col.f32.tf32.tf32.f32 "
        "{%0,%1,%2,%3}, {%4,%5,%6,%7}, {%8,%9}, {%0,%1,%2,%3};"
        : "+f"(d[0]), "+f"(d[1]), "+f"(d[2]), "+f"(d[3])
        : "r"(a[0]), "r"(a[1]), "r"(a[2]), "r"(a[3]), "r"(bf[0]), "r"(bf[1]));
}

// ---------------- prologue kernels ----------------
__global__ void style_kernel(const float* __restrict__ w, const float* __restrict__ lw,
                             const float* __restrict__ lb) {
    __shared__ float ws[WD_];
    int b = blockIdx.x, o = threadIdx.x;
    ws[o] = w[b * WD_ + o];
    __syncthreads();
    const float* lwr = lw + (size_t)o * WD_;
    float acc = lb[o];
#pragma unroll 8
    for (int d = 0; d < WD_; d++) acc = fmaf(ws[d], lwr[d], acc);
    g_style[b * C_ + o] = acc;
}

__global__ void s_kernel(const float* __restrict__ cw) {
    int o = blockIdx.x, i = threadIdx.x;
    const float* p = cw + ((size_t)o * C_ + i) * 9;
    float s = 0.f;
#pragma unroll
    for (int k = 0; k < 9; k++) { float v = p[k]; s = fmaf(v, v, s); }
    g_S[o * C_ + i] = s;
}

__global__ void rdenom_kernel() {
    __shared__ float st2[C_];
    int b = blockIdx.x, o = threadIdx.x;
    float s = g_style[b * C_ + o];
    st2[o] = s * s;
    __syncthreads();
    const float* Sr = g_S + (size_t)o * C_;
    float acc = EPS_;
#pragma unroll 8
    for (int i = 0; i < C_; i++) acc = fmaf(Sr[i], st2[i], acc);
    g_rdenom[b * C_ + o] = rsqrtf(acc);
}

// cw_t[tap][o][i] = tf32(cw[o][i][tap])
__global__ void transpose_w_kernel(const float* __restrict__ cw) {
    int o = blockIdx.x, i = threadIdx.x;
    const float* p = cw + ((size_t)o * C_ + i) * 9;
#pragma unroll
    for (int t = 0; t < 9; t++)
        g_cwt[((size_t)t * C_ + o) * C_ + i] = tf32r(p[t]);
}

// x_t[b][p][i] = tf32(x[b][i][p] * style[b][i])
__global__ void transpose_x_kernel(const float* __restrict__ x) {
    __shared__ float t[32][33];
    const int b = blockIdx.z, cb = blockIdx.y * 32, pb = blockIdx.x * 32;
    const int tx = threadIdx.x, ty = threadIdx.y;
#pragma unroll
    for (int r = 0; r < 4; r++) {
        int ch = cb + ty + r * 8;
        t[ty + r * 8][tx] = x[((size_t)(b * C_ + ch)) * HW_ + pb + tx];
    }
    __syncthreads();
#pragma unroll
    for (int r = 0; r < 4; r++) {
        int p = pb + ty + r * 8;
        int ch = cb + tx;
        float v = t[tx][ty + r * 8] * g_style[b * C_ + ch];
        g_xt[((size_t)b * HW_ + p) * C_ + ch] = tf32r(v);
    }
}

// ---------------- main conv kernel: tf32 mma.sync implicit GEMM ----------------
// CTA: M=128 out-ch x N=128 pixels. K = 9 taps x 16 chunks of 32 ch (144 chunks).
// 8 warps: warp_m (2) x warp_n (4); warp tile 64 x 32 = 4x4 m16n8k8 tiles x 4 ksteps.
// Smem tiles [128][36] fp32, stride-36 padding: conflict-free frag loads & fills.
#define STRIDE 36
#define TILE_F (128 * STRIDE)           // floats per tile (4608)
#define STAGE_F (2 * TILE_F)            // A + B per stage (9216)
#define SMEM_BYTES (2 * STAGE_F * 4)    // 73728

__global__ void __launch_bounds__(256)
conv_mma_kernel(float* __restrict__ out) {
    extern __shared__ float smf[];
    const int tid  = threadIdx.x;
    const int b    = blockIdx.z;
    const int oc0  = blockIdx.y * 128;
    const int P0   = blockIdx.x * 128;
    const int lane = tid & 31;
    const int wrp  = tid >> 5;
    const int wm   = wrp & 1;           // 0..1 -> 64-row block
    const int wn   = wrp >> 1;          // 0..3 -> 32-col block
    const int qr   = lane >> 2;         // 0..7
    const int qc   = lane & 3;          // 0..3

    // per-thread fill coordinates (4 cp.async each for A and B)
    const int fr = tid >> 3;            // 0..31 (+32 per j)
    const int fc = (tid & 7) * 4;       // float offset within 32-ch chunk

    const float* Aglob = g_cwt;         // [tap][o][i]
    const float* Bglob = g_xt + (size_t)b * HW_ * C_;

    const uint32_t sA = smem_u32(smf);

    float acc[4][4][4];
#pragma unroll
    for (int mt = 0; mt < 4; mt++)
#pragma unroll
        for (int nt = 0; nt < 4; nt++)
#pragma unroll
            for (int r = 0; r < 4; r++) acc[mt][nt][r] = 0.f;

    // --- chunk issue ---
    auto issue = [&](int it) {
        const int s   = it & 1;
        const int tap = it >> 4;
        const int ci0 = (it & 15) << 5;
        const int dy  = tap / 3 - 1;
        const int dx  = tap % 3 - 1;
        const int shift = dy * W64 + dx;
        const uint32_t stA = sA + (uint32_t)(s * STAGE_F) * 4;
        const uint32_t stB = stA + TILE_F * 4;
        const float* Ab = Aglob + ((size_t)tap * C_ + oc0) * C_ + ci0 + fc;
        const float* Bb = Bglob + ci0 + fc;
#pragma unroll
        for (int j = 0; j < 4; j++) {
            int r = fr + j * 32;
            cp16(stA + (uint32_t)(r * STRIDE + fc) * 4, Ab + (size_t)r * C_, 16);
        }
#pragma unroll
        for (int j = 0; j < 4; j++) {
            int n = fr + j * 32;
            int p = P0 + n;
            int y = p >> 6, xc = p & 63;
            bool ok = ((unsigned)(y + dy) < W64) && ((unsigned)(xc + dx) < W64);
            const float* src = Bb + (size_t)(ok ? (p + shift) : p) * C_;
            cp16(stB + (uint32_t)(n * STRIDE + fc) * 4, src, ok ? 16u : 0u);
        }
        cp_commit();
    };

    issue(0);

    for (int it = 0; it < 144; it++) {
        if (it + 1 < 144) { issue(it + 1); cp_wait<1>(); }
        else              { cp_wait<0>(); }
        __syncthreads();

        const float* As = smf + (it & 1) * STAGE_F;
        const float* Bs = As + TILE_F;
        const float* Arow = As + (wm * 64 + qr) * STRIDE + qc;
        const float* Brow = Bs + (wn * 32 + qr) * STRIDE + qc;

#pragma unroll
        for (int ks = 0; ks < 4; ks++) {
            const int k0 = ks * 8;
            uint32_t a[4][4], bf[4][2];
#pragma unroll
            for (int mt = 0; mt < 4; mt++) {
                const float* p = Arow + mt * 16 * STRIDE + k0;
                a[mt][0] = __float_as_uint(p[0]);
                a[mt][1] = __float_as_uint(p[8 * STRIDE]);
                a[mt][2] = __float_as_uint(p[4]);
                a[mt][3] = __float_as_uint(p[8 * STRIDE + 4]);
            }
#pragma unroll
            for (int nt = 0; nt < 4; nt++) {
                const float* p = Brow + nt * 8 * STRIDE + k0;
                bf[nt][0] = __float_as_uint(p[0]);
                bf[nt][1] = __float_as_uint(p[4]);
            }
#pragma unroll
            for (int mt = 0; mt < 4; mt++)
#pragma unroll
                for (int nt = 0; nt < 4; nt++)
                    mma_tf32(acc[mt][nt], a[mt], bf[nt]);
        }
        __syncthreads();
    }

    // --- epilogue: demodulate + store ---
#pragma unroll
    for (int mt = 0; mt < 4; mt++) {
        const int oc_r = oc0 + wm * 64 + mt * 16 + qr;
        const float rd0 = g_rdenom[b * C_ + oc_r];
        const float rd1 = g_rdenom[b * C_ + oc_r + 8];
        float* o0 = out + ((size_t)(b * C_ + oc_r)) * HW_ + P0 + wn * 32 + qc * 2;
        float* o1 = o0 + (size_t)8 * HW_;
#pragma unroll
        for (int nt = 0; nt < 4; nt++) {
            float2 v0 = make_float2(acc[mt][nt][0] * rd0, acc[mt][nt][1] * rd0);
            float2 v1 = make_float2(acc[mt][nt][2] * rd1, acc[mt][nt][3] * rd1);
            *(float2*)(o0 + nt * 8) = v0;
            *(float2*)(o1 + nt * 8) = v1;
        }
    }
}

// ---------------- launch ----------------
extern "C" void kernel_launch(void* const* d_in, const int* in_sizes, int n_in,
                              void* d_out, int out_size) {
    const float* x  = (const float*)d_in[0];   // (16,512,64,64)
    const float* w  = (const float*)d_in[1];   // (16,512)
    const float* cw = (const float*)d_in[2];   // (512,512,3,3)
    const float* lw = (const float*)d_in[3];   // (512,512)
    const float* lb = (const float*)d_in[4];   // (512,)
    float* out = (float*)d_out;                // (16,512,64,64) fp32

    cudaFuncSetAttribute(conv_mma_kernel,
                         cudaFuncAttributeMaxDynamicSharedMemorySize, SMEM_BYTES);

    style_kernel<<<B_, C_>>>(w, lw, lb);
    s_kernel<<<C_, C_>>>(cw);
    rdenom_kernel<<<B_, C_>>>();
    transpose_w_kernel<<<C_, C_>>>(cw);
    transpose_x_kernel<<<dim3(HW_ / 32, C_ / 32, B_), dim3(32, 8)>>>(x);

    conv_mma_kernel<<<dim3(HW_ / 128, C_ / 128, B_), 256, SMEM_BYTES>>>(out);
}

// round 5
// speedup vs baseline: 6.1886x; 1.6738x over previous
#include <cuda_runtime.h>
#include <cuda_fp16.h>
#include <cstdint>

#define B_   16
#define C_   512
#define HW_  4096
#define W64  64
#define WD_  512
#define EPS_ 1e-6f

// ---------------- scratch (__device__ globals; no runtime alloc) ----------------
__device__ float  g_style[B_ * C_];
__device__ float  g_S[C_ * C_];
__device__ float  g_rdenom[B_ * C_];
__device__ __half g_xt[(size_t)B_ * HW_ * C_];   // (b, p, i): style-scaled, fp16
__device__ __half g_cwt[(size_t)9 * C_ * C_];    // (tap, o, i): fp16

// ---------------- helpers ----------------
__device__ __forceinline__ uint32_t smem_u32(const void* p) {
    uint32_t a;
    asm("{ .reg .u64 t; cvta.to.shared.u64 t, %1; cvt.u32.u64 %0, t; }" : "=r"(a) : "l"(p));
    return a;
}
__device__ __forceinline__ void cp16(uint32_t dst, const void* src, uint32_t src_bytes) {
    asm volatile("cp.async.cg.shared.global [%0], [%1], 16, %2;"
                 :: "r"(dst), "l"(src), "r"(src_bytes));
}
template <int N>
__device__ __forceinline__ void cp_wait() {
    asm volatile("cp.async.wait_group %0;" :: "n"(N) : "memory");
}
__device__ __forceinline__ void cp_commit() {
    asm volatile("cp.async.commit_group;" ::: "memory");
}
__device__ __forceinline__ void ldsm4(uint32_t* r, uint32_t addr) {
    asm volatile("ldmatrix.sync.aligned.m8n8.x4.shared.b16 {%0,%1,%2,%3}, [%4];"
                 : "=r"(r[0]), "=r"(r[1]), "=r"(r[2]), "=r"(r[3]) : "r"(addr));
}
__device__ __forceinline__ void mma_f16(float* d, const uint32_t* a, const uint32_t* bf) {
    asm volatile(
        "mma.sync.aligned.m16n8k16.row.col.f32.f16.f16.f32 "
        "{%0,%1,%2,%3}, {%4,%5,%6,%7}, {%8,%9}, {%0,%1,%2,%3};"
        : "+f"(d[0]), "+f"(d[1]), "+f"(d[2]), "+f"(d[3])
        : "r"(a[0]), "r"(a[1]), "r"(a[2]), "r"(a[3]), "r"(bf[0]), "r"(bf[1]));
}

// ---------------- prologue kernels ----------------
__global__ void style_kernel(const float* __restrict__ w, const float* __restrict__ lw,
                             const float* __restrict__ lb) {
    __shared__ float ws[WD_];
    int b = blockIdx.x, o = threadIdx.x;
    ws[o] = w[b * WD_ + o];
    __syncthreads();
    const float* lwr = lw + (size_t)o * WD_;
    float acc = lb[o];
#pragma unroll 8
    for (int d = 0; d < WD_; d++) acc = fmaf(ws[d], lwr[d], acc);
    g_style[b * C_ + o] = acc;
}

__global__ void s_kernel(const float* __restrict__ cw) {
    int o = blockIdx.x, i = threadIdx.x;
    const float* p = cw + ((size_t)o * C_ + i) * 9;
    float s = 0.f;
#pragma unroll
    for (int k = 0; k < 9; k++) { float v = p[k]; s = fmaf(v, v, s); }
    g_S[o * C_ + i] = s;
}

__global__ void rdenom_kernel() {
    __shared__ float st2[C_];
    int b = blockIdx.x, o = threadIdx.x;
    float s = g_style[b * C_ + o];
    st2[o] = s * s;
    __syncthreads();
    const float* Sr = g_S + (size_t)o * C_;
    float acc = EPS_;
#pragma unroll 8
    for (int i = 0; i < C_; i++) acc = fmaf(Sr[i], st2[i], acc);
    g_rdenom[b * C_ + o] = rsqrtf(acc);
}

// cw_t[tap][o][i] = fp16(cw[o][i][tap])
__global__ void transpose_w_kernel(const float* __restrict__ cw) {
    int o = blockIdx.x, i = threadIdx.x;
    const float* p = cw + ((size_t)o * C_ + i) * 9;
#pragma unroll
    for (int t = 0; t < 9; t++)
        g_cwt[((size_t)t * C_ + o) * C_ + i] = __float2half_rn(p[t]);
}

// x_t[b][p][i] = fp16(x[b][i][p] * style[b][i])
__global__ void transpose_x_kernel(const float* __restrict__ x) {
    __shared__ float t[32][33];
    const int b = blockIdx.z, cb = blockIdx.y * 32, pb = blockIdx.x * 32;
    const int tx = threadIdx.x, ty = threadIdx.y;
#pragma unroll
    for (int r = 0; r < 4; r++) {
        int ch = cb + ty + r * 8;
        t[ty + r * 8][tx] = x[((size_t)(b * C_ + ch)) * HW_ + pb + tx];
    }
    __syncthreads();
#pragma unroll
    for (int r = 0; r < 4; r++) {
        int p = pb + ty + r * 8;
        int ch = cb + tx;
        float v = t[tx][ty + r * 8] * g_style[b * C_ + ch];
        g_xt[((size_t)b * HW_ + p) * C_ + ch] = __float2half_rn(v);
    }
}

// ---------------- main conv kernel: fp16 mma.sync implicit GEMM ----------------
// CTA: M=128 out-ch x N=128 pixels. K = 9 taps x 16 chunks of 32 ch (144 chunks).
// 8 warps: (wm 2) x (wn 4); warp tile 64 x 32 = 4x4 m16n8k16 tiles x 2 ksteps.
// fp16 smem tiles [128][40] (80B rows: 16B-aligned, disjoint bank groups),
// 3-stage cp.async pipeline, ldmatrix fragment loads.
#define STR    40                          // halves per row (80B)
#define TILE_H (128 * STR)                 // halves per tile (5120)
#define STAGE_B (2 * TILE_H * 2)           // bytes per stage: A + B (20480)
#define NSTAGE 3
#define SMEM_BYTES (NSTAGE * STAGE_B)      // 61440

__global__ void __launch_bounds__(256, 2)
conv_mma_kernel(float* __restrict__ out) {
    extern __shared__ __half smh[];
    const int tid  = threadIdx.x;
    const int b    = blockIdx.z;
    const int oc0  = blockIdx.y * 128;
    const int P0   = blockIdx.x * 128;
    const int lane = tid & 31;
    const int wrp  = tid >> 5;
    const int wm   = wrp & 1;              // 0..1 -> 64-row block
    const int wn   = wrp >> 1;             // 0..3 -> 32-col block
    const int qr   = lane >> 2;            // 0..7
    const int qc   = lane & 3;             // 0..3

    // fill coords: thread covers rows (t>>2)+{0,64}, 8 halves at (t&3)*8
    const int fr = tid >> 2;               // 0..63
    const int fch = (tid & 3) * 8;         // half offset in 32-ch chunk

    const __half* Aglob = g_cwt;
    const __half* Bglob = g_xt + (size_t)b * HW_ * C_;
    const uint32_t sbase = smem_u32(smh);

    float acc[4][4][4];
#pragma unroll
    for (int mt = 0; mt < 4; mt++)
#pragma unroll
        for (int nt = 0; nt < 4; nt++)
#pragma unroll
            for (int r = 0; r < 4; r++) acc[mt][nt][r] = 0.f;

    auto issue = [&](int it) {
        const int s   = it % NSTAGE;
        const int tap = it >> 4;
        const int ci0 = (it & 15) << 5;
        const int dy  = tap / 3 - 1;
        const int dx  = tap % 3 - 1;
        const int shift = dy * W64 + dx;
        const uint32_t stA = sbase + (uint32_t)s * STAGE_B;
        const uint32_t stB = stA + TILE_H * 2;
        const __half* Ab = Aglob + ((size_t)tap * C_ + oc0) * C_ + ci0 + fch;
        const __half* Bb = Bglob + ci0 + fch;
#pragma unroll
        for (int j = 0; j < 2; j++) {
            int r = fr + j * 64;
            cp16(stA + (uint32_t)(r * STR + fch) * 2, Ab + (size_t)r * C_, 16);
        }
#pragma unroll
        for (int j = 0; j < 2; j++) {
            int n = fr + j * 64;
            int p = P0 + n;
            int y = p >> 6, xc = p & 63;
            bool ok = ((unsigned)(y + dy) < W64) && ((unsigned)(xc + dx) < W64);
            const __half* src = Bb + (size_t)(ok ? (p + shift) : p) * C_;
            cp16(stB + (uint32_t)(n * STR + fch) * 2, src, ok ? 16u : 0u);
        }
        cp_commit();
    };

    issue(0);
    issue(1);

    for (int it = 0; it < 144; it++) {
        if (it + 2 < 144) { issue(it + 2); cp_wait<1>(); }
        else              { cp_wait<0>(); }
        __syncthreads();

        const int s = it % NSTAGE;
        const uint32_t stA = sbase + (uint32_t)s * STAGE_B;
        const uint32_t stB = stA + TILE_H * 2;

#pragma unroll
        for (int ks = 0; ks < 2; ks++) {
            const int k0 = ks * 16;
            uint32_t a[4][4], bf[2][4];
#pragma unroll
            for (int mt = 0; mt < 4; mt++) {
                int row  = wm * 64 + mt * 16 + (lane & 15);
                int colh = k0 + ((lane >> 4) << 3);
                ldsm4(a[mt], stA + (uint32_t)(row * STR + colh) * 2);
            }
#pragma unroll
            for (int pp = 0; pp < 2; pp++) {
                int sub  = lane >> 3;
                int n    = wn * 32 + (pp * 2 + (sub >> 1)) * 8 + (lane & 7);
                int colh = k0 + ((sub & 1) << 3);
                ldsm4(bf[pp], stB + (uint32_t)(n * STR + colh) * 2);
            }
#pragma unroll
            for (int mt = 0; mt < 4; mt++) {
#pragma unroll
                for (int nt = 0; nt < 4; nt++)
                    mma_f16(acc[mt][nt], a[mt], &bf[nt >> 1][(nt & 1) * 2]);
            }
        }
        __syncthreads();
    }

    // --- epilogue: demodulate + store ---
#pragma unroll
    for (int mt = 0; mt < 4; mt++) {
        const int oc_r = oc0 + wm * 64 + mt * 16 + qr;
        const float rd0 = g_rdenom[b * C_ + oc_r];
        const float rd1 = g_rdenom[b * C_ + oc_r + 8];
        float* o0 = out + ((size_t)(b * C_ + oc_r)) * HW_ + P0 + wn * 32 + qc * 2;
        float* o1 = o0 + (size_t)8 * HW_;
#pragma unroll
        for (int nt = 0; nt < 4; nt++) {
            float2 v0 = make_float2(acc[mt][nt][0] * rd0, acc[mt][nt][1] * rd0);
            float2 v1 = make_float2(acc[mt][nt][2] * rd1, acc[mt][nt][3] * rd1);
            *(float2*)(o0 + nt * 8) = v0;
            *(float2*)(o1 + nt * 8) = v1;
        }
    }
}

// ---------------- launch ----------------
extern "C" void kernel_launch(void* const* d_in, const int* in_sizes, int n_in,
                              void* d_out, int out_size) {
    const float* x  = (const float*)d_in[0];   // (16,512,64,64)
    const float* w  = (const float*)d_in[1];   // (16,512)
    const float* cw = (const float*)d_in[2];   // (512,512,3,3)
    const float* lw = (const float*)d_in[3];   // (512,512)
    const float* lb = (const float*)d_in[4];   // (512,)
    float* out = (float*)d_out;                // (16,512,64,64) fp32

    cudaFuncSetAttribute(conv_mma_kernel,
                         cudaFuncAttributeMaxDynamicSharedMemorySize, SMEM_BYTES);

    style_kernel<<<B_, C_>>>(w, lw, lb);
    s_kernel<<<C_, C_>>>(cw);
    rdenom_kernel<<<B_, C_>>>();
    transpose_w_kernel<<<C_, C_>>>(cw);
    transpose_x_kernel<<<dim3(HW_ / 32, C_ / 32, B_), dim3(32, 8)>>>(x);

    conv_mma_kernel<<<dim3(HW_ / 128, C_ / 128, B_), 256, SMEM_BYTES>>>(out);
}

// round 6
// speedup vs baseline: 7.5449x; 1.2192x over previous
#include <cuda_runtime.h>
#include <cuda_fp16.h>
#include <cstdint>

#define B_   16
#define C_   512
#define HW_  4096
#define W64  64
#define WD_  512
#define EPS_ 1e-6f
#define NT_  16384           // total Winograd tiles = B_ * 1024
#define NCF  16              // Winograd coefficients (4x4)

// ---------------- scratch (__device__ globals; no runtime alloc) ----------------
__device__ float  g_style[B_ * C_];
__device__ float  g_S[C_ * C_];
__device__ float  g_rdenom[B_ * C_];
__device__ __half g_U[(size_t)NCF * C_ * C_];        // (coef, oc, ic) fp16
__device__ __half g_V[(size_t)NCF * NT_ * C_];       // (coef, n, ic)  fp16
__device__ float  g_M[(size_t)NCF * C_ * NT_];       // (coef, oc, n)  fp32

// ---------------- helpers ----------------
__device__ __forceinline__ uint32_t smem_u32(const void* p) {
    uint32_t a;
    asm("{ .reg .u64 t; cvta.to.shared.u64 t, %1; cvt.u32.u64 %0, t; }" : "=r"(a) : "l"(p));
    return a;
}
__device__ __forceinline__ void cp16(uint32_t dst, const void* src) {
    asm volatile("cp.async.cg.shared.global [%0], [%1], 16;" :: "r"(dst), "l"(src));
}
template <int N>
__device__ __forceinline__ void cp_wait() {
    asm volatile("cp.async.wait_group %0;" :: "n"(N) : "memory");
}
__device__ __forceinline__ void cp_commit() {
    asm volatile("cp.async.commit_group;" ::: "memory");
}
__device__ __forceinline__ void ldsm4(uint32_t* r, uint32_t addr) {
    asm volatile("ldmatrix.sync.aligned.m8n8.x4.shared.b16 {%0,%1,%2,%3}, [%4];"
                 : "=r"(r[0]), "=r"(r[1]), "=r"(r[2]), "=r"(r[3]) : "r"(addr));
}
__device__ __forceinline__ void mma_f16(float* d, const uint32_t* a, const uint32_t* bf) {
    asm volatile(
        "mma.sync.aligned.m16n8k16.row.col.f32.f16.f16.f32 "
        "{%0,%1,%2,%3}, {%4,%5,%6,%7}, {%8,%9}, {%0,%1,%2,%3};"
        : "+f"(d[0]), "+f"(d[1]), "+f"(d[2]), "+f"(d[3])
        : "r"(a[0]), "r"(a[1]), "r"(a[2]), "r"(a[3]), "r"(bf[0]), "r"(bf[1]));
}

// ---------------- prologue: style / S / rdenom ----------------
__global__ void style_kernel(const float* __restrict__ w, const float* __restrict__ lw,
                             const float* __restrict__ lb) {
    __shared__ float ws[WD_];
    int b = blockIdx.x, o = threadIdx.x;
    ws[o] = w[b * WD_ + o];
    __syncthreads();
    const float* lwr = lw + (size_t)o * WD_;
    float acc = lb[o];
#pragma unroll 8
    for (int d = 0; d < WD_; d++) acc = fmaf(ws[d], lwr[d], acc);
    g_style[b * C_ + o] = acc;
}

__global__ void s_kernel(const float* __restrict__ cw) {
    int o = blockIdx.x, i = threadIdx.x;
    const float* p = cw + ((size_t)o * C_ + i) * 9;
    float s = 0.f;
#pragma unroll
    for (int k = 0; k < 9; k++) { float v = p[k]; s = fmaf(v, v, s); }
    g_S[o * C_ + i] = s;
}

__global__ void rdenom_kernel() {
    __shared__ float st2[C_];
    int b = blockIdx.x, o = threadIdx.x;
    float s = g_style[b * C_ + o];
    st2[o] = s * s;
    __syncthreads();
    const float* Sr = g_S + (size_t)o * C_;
    float acc = EPS_;
#pragma unroll 8
    for (int i = 0; i < C_; i++) acc = fmaf(Sr[i], st2[i], acc);
    g_rdenom[b * C_ + o] = rsqrtf(acc);
}

// ---------------- Winograd weight transform: U = G g G^T ----------------
__global__ void wino_w_kernel(const float* __restrict__ cw) {
    int o = blockIdx.x, i = threadIdx.x;
    const float* g = cw + ((size_t)o * C_ + i) * 9;
    float q[3][3];
#pragma unroll
    for (int r = 0; r < 3; r++)
#pragma unroll
        for (int c = 0; c < 3; c++) q[r][c] = g[r * 3 + c];
    float t[4][3];
#pragma unroll
    for (int c = 0; c < 3; c++) {
        t[0][c] = q[0][c];
        t[1][c] = 0.5f * (q[0][c] + q[1][c] + q[2][c]);
        t[2][c] = 0.5f * (q[0][c] - q[1][c] + q[2][c]);
        t[3][c] = q[2][c];
    }
#pragma unroll
    for (int r = 0; r < 4; r++) {
        float u0 = t[r][0];
        float u1 = 0.5f * (t[r][0] + t[r][1] + t[r][2]);
        float u2 = 0.5f * (t[r][0] - t[r][1] + t[r][2]);
        float u3 = t[r][2];
        g_U[((size_t)(r * 4 + 0) * C_ + o) * C_ + i] = __float2half_rn(u0);
        g_U[((size_t)(r * 4 + 1) * C_ + o) * C_ + i] = __float2half_rn(u1);
        g_U[((size_t)(r * 4 + 2) * C_ + o) * C_ + i] = __float2half_rn(u2);
        g_U[((size_t)(r * 4 + 3) * C_ + o) * C_ + i] = __float2half_rn(u3);
    }
}

// ---------------- Winograd input transform: V = B^T d B (style folded) ----------------
// Block: (tile-row ty, 32-channel group, batch). 256 threads.
__global__ void __launch_bounds__(256)
wino_x_kernel(const float* __restrict__ x) {
    __shared__ float xs[4][32][71];
    const int b = blockIdx.z, chg = blockIdx.y * 32, ty = blockIdx.x;
    const int tid = threadIdx.x;

    for (int idx = tid; idx < 4 * 32 * 68; idx += 256) {
        int r   = idx / (32 * 68);
        int rem = idx % (32 * 68);
        int ch  = rem / 68;
        int col = rem % 68;
        if (col < 66) {
            int y  = ty * 2 - 1 + r;
            int xg = col - 1;
            float v = 0.f;
            if ((unsigned)y < W64 && (unsigned)xg < W64)
                v = x[((size_t)(b * C_ + chg + ch)) * HW_ + y * W64 + xg];
            xs[r][ch][col] = v;
        }
    }
    __syncthreads();

    const int tx  = tid >> 3;          // 0..31 tile col
    const int ch4 = (tid & 7) * 4;     // 0,4,...,28
    const int n   = b * 1024 + ty * 32 + tx;

    unsigned short hs[NCF][4];
#pragma unroll
    for (int cc = 0; cc < 4; cc++) {
        const int ch = ch4 + cc;
        const float st = g_style[b * C_ + chg + ch];
        float d[4][4];
#pragma unroll
        for (int r = 0; r < 4; r++)
#pragma unroll
            for (int c = 0; c < 4; c++) d[r][c] = xs[r][ch][2 * tx + c];
        float wv[4][4];
#pragma unroll
        for (int c = 0; c < 4; c++) {
            wv[0][c] = d[0][c] - d[2][c];
            wv[1][c] = d[1][c] + d[2][c];
            wv[2][c] = d[2][c] - d[1][c];
            wv[3][c] = d[1][c] - d[3][c];
        }
#pragma unroll
        for (int r = 0; r < 4; r++) {
            float v0 = wv[r][0] - wv[r][2];
            float v1 = wv[r][1] + wv[r][2];
            float v2 = wv[r][2] - wv[r][1];
            float v3 = wv[r][1] - wv[r][3];
            hs[r * 4 + 0][cc] = __half_as_ushort(__float2half_rn(v0 * st));
            hs[r * 4 + 1][cc] = __half_as_ushort(__float2half_rn(v1 * st));
            hs[r * 4 + 2][cc] = __half_as_ushort(__float2half_rn(v2 * st));
            hs[r * 4 + 3][cc] = __half_as_ushort(__float2half_rn(v3 * st));
        }
    }
#pragma unroll
    for (int c = 0; c < NCF; c++) {
        uint2 val;
        val.x = (uint32_t)hs[c][0] | ((uint32_t)hs[c][1] << 16);
        val.y = (uint32_t)hs[c][2] | ((uint32_t)hs[c][3] << 16);
        *(uint2*)(g_V + ((size_t)c * NT_ + n) * C_ + chg + ch4) = val;
    }
}

// ---------------- Winograd GEMM: M[coef] = U[coef] @ V[coef]^T ----------------
// CTA 128 oc x 128 n; K = 512 (16 chunks of 32). Same fp16 mma pipeline as R5.
#define STR    40
#define TILE_H (128 * STR)
#define STAGE_B (2 * TILE_H * 2)
#define NSTAGE 3
#define SMEM_BYTES (NSTAGE * STAGE_B)      // 61440

__global__ void __launch_bounds__(256, 2)
wino_gemm_kernel() {
    extern __shared__ __half smh[];
    const int tid  = threadIdx.x;
    const int coef = blockIdx.z;
    const int oc0  = blockIdx.y * 128;
    const int n0   = blockIdx.x * 128;
    const int lane = tid & 31;
    const int wrp  = tid >> 5;
    const int wm   = wrp & 1;
    const int wn   = wrp >> 1;
    const int qr   = lane >> 2;
    const int qc   = lane & 3;
    const int fr   = tid >> 2;
    const int fch  = (tid & 3) * 8;

    const __half* Ag = g_U + ((size_t)coef * C_ + oc0) * C_;
    const __half* Bg = g_V + ((size_t)coef * NT_ + n0) * C_;
    const uint32_t sbase = smem_u32(smh);

    float acc[4][4][4];
#pragma unroll
    for (int mt = 0; mt < 4; mt++)
#pragma unroll
        for (int nt = 0; nt < 4; nt++)
#pragma unroll
            for (int r = 0; r < 4; r++) acc[mt][nt][r] = 0.f;

    auto issue = [&](int it) {
        const int s   = it % NSTAGE;
        const int ci0 = it << 5;
        const uint32_t stA = sbase + (uint32_t)s * STAGE_B;
        const uint32_t stB = stA + TILE_H * 2;
        const __half* Ab = Ag + ci0 + fch;
        const __half* Bb = Bg + ci0 + fch;
#pragma unroll
        for (int j = 0; j < 2; j++) {
            int r = fr + j * 64;
            cp16(stA + (uint32_t)(r * STR + fch) * 2, Ab + (size_t)r * C_);
        }
#pragma unroll
        for (int j = 0; j < 2; j++) {
            int n = fr + j * 64;
            cp16(stB + (uint32_t)(n * STR + fch) * 2, Bb + (size_t)n * C_);
        }
        cp_commit();
    };

    issue(0);
    issue(1);

    for (int it = 0; it < 16; it++) {
        if (it + 2 < 16) { issue(it + 2); cp_wait<1>(); }
        else             { cp_wait<0>(); }
        __syncthreads();

        const int s = it % NSTAGE;
        const uint32_t stA = sbase + (uint32_t)s * STAGE_B;
        const uint32_t stB = stA + TILE_H * 2;

#pragma unroll
        for (int ks = 0; ks < 2; ks++) {
            const int k0 = ks * 16;
            uint32_t a[4][4], bf[2][4];
#pragma unroll
            for (int mt = 0; mt < 4; mt++) {
                int row  = wm * 64 + mt * 16 + (lane & 15);
                int colh = k0 + ((lane >> 4) << 3);
                ldsm4(a[mt], stA + (uint32_t)(row * STR + colh) * 2);
            }
#pragma unroll
            for (int pp = 0; pp < 2; pp++) {
                int sub  = lane >> 3;
                int n    = wn * 32 + (pp * 2 + (sub >> 1)) * 8 + (lane & 7);
                int colh = k0 + ((sub & 1) << 3);
                ldsm4(bf[pp], stB + (uint32_t)(n * STR + colh) * 2);
            }
#pragma unroll
            for (int mt = 0; mt < 4; mt++) {
#pragma unroll
                for (int nt = 0; nt < 4; nt++)
                    mma_f16(acc[mt][nt], a[mt], &bf[nt >> 1][(nt & 1) * 2]);
            }
        }
        __syncthreads();
    }

    // epilogue: store M[coef][oc][n] fp32
#pragma unroll
    for (int mt = 0; mt < 4; mt++) {
        const int oc_r = oc0 + wm * 64 + mt * 16 + qr;
        float* o0 = g_M + ((size_t)coef * C_ + oc_r) * NT_ + n0 + wn * 32 + qc * 2;
        float* o1 = o0 + (size_t)8 * NT_;
#pragma unroll
        for (int nt = 0; nt < 4; nt++) {
            *(float2*)(o0 + nt * 8) = make_float2(acc[mt][nt][0], acc[mt][nt][1]);
            *(float2*)(o1 + nt * 8) = make_float2(acc[mt][nt][2], acc[mt][nt][3]);
        }
    }
}

// ---------------- inverse transform: Y = A^T M A, demodulate, store ----------------
__global__ void __launch_bounds__(256)
wino_inv_kernel(float* __restrict__ out) {
    const int n  = blockIdx.x * 256 + threadIdx.x;   // 0..16383
    const int oc = blockIdx.y;
    const int b  = n >> 10, t = n & 1023;
    const int ty = t >> 5, tx = t & 31;

    float m[16];
#pragma unroll
    for (int c = 0; c < NCF; c++)
        m[c] = g_M[((size_t)c * C_ + oc) * NT_ + n];

    float z0[4], z1[4];
#pragma unroll
    for (int k = 0; k < 4; k++) {
        z0[k] = m[k * 4 + 0] + m[k * 4 + 1] + m[k * 4 + 2];
        z1[k] = m[k * 4 + 1] - m[k * 4 + 2] - m[k * 4 + 3];
    }
    const float rd = g_rdenom[b * C_ + oc];
    float y00 = (z0[0] + z0[1] + z0[2]) * rd;
    float y01 = (z1[0] + z1[1] + z1[2]) * rd;
    float y10 = (z0[1] - z0[2] - z0[3]) * rd;
    float y11 = (z1[1] - z1[2] - z1[3]) * rd;

    float* op = out + ((size_t)(b * C_ + oc)) * HW_ + (ty * 2) * W64 + tx * 2;
    *(float2*)op          = make_float2(y00, y01);
    *(float2*)(op + W64)  = make_float2(y10, y11);
}

// ---------------- launch ----------------
extern "C" void kernel_launch(void* const* d_in, const int* in_sizes, int n_in,
                              void* d_out, int out_size) {
    const float* x  = (const float*)d_in[0];   // (16,512,64,64)
    const float* w  = (const float*)d_in[1];   // (16,512)
    const float* cw = (const float*)d_in[2];   // (512,512,3,3)
    const float* lw = (const float*)d_in[3];   // (512,512)
    const float* lb = (const float*)d_in[4];   // (512,)
    float* out = (float*)d_out;                // (16,512,64,64) fp32

    cudaFuncSetAttribute(wino_gemm_kernel,
                         cudaFuncAttributeMaxDynamicSharedMemorySize, SMEM_BYTES);

    style_kernel<<<B_, C_>>>(w, lw, lb);
    s_kernel<<<C_, C_>>>(cw);
    rdenom_kernel<<<B_, C_>>>();
    wino_w_kernel<<<C_, C_>>>(cw);
    wino_x_kernel<<<dim3(32, C_ / 32, B_), 256>>>(x);
    wino_gemm_kernel<<<dim3(NT_ / 128, C_ / 128, NCF), 256, SMEM_BYTES>>>();
    wino_inv_kernel<<<dim3(NT_ / 256, C_), 256>>>(out);
}